// round 16
// baseline (speedup 1.0000x reference)
#include <cuda_runtime.h>

// ---------------- problem constants (fixed shapes) ----------------
#define B_    4
#define D_    118
#define H_    32              // == warp size: lane <-> h
#define W_    88
#define C_    80
#define NX_   360
#define NY_   360
#define XY_   (NX_ * NY_)     // 129600
#define NCOLB (D_ * W_)       // 10,384 columns per batch (divisible by 8)
#define NCOL  (B_ * NCOLB)    // 41,536 ray columns
#define NGRP  (NCOL / 8)      // 5192 column groups (8 cols each)
#define GPB   4               // groups per block
#define GRID_ (NGRP / GPB)    // 1298 blocks
#define ZBLKS 444u            // zero-duty blocks (<= 4/SM * 148 = 592 resident)
#define OUT_N4 ((unsigned)(B_ * C_ * XY_ / 4))   // 10,368,000 float4

// cross-launch counters: zero at module load; last-exiting block resets them,
// so every graph replay starts from the same (0,0) state.
__device__ unsigned g_done;
__device__ unsigned g_exit;

// ---------------- fused kernel: zero + scatter with device-side join -------
// Structural fact (validated R5-R15): combine[0][1] == combine[1][1] == 0
// exactly in fp32, so gx,gy are identical across the 32 h's of a (b,d,w)
// column; only the cz==0 test varies with h.
//
// Overlap design (replaces PDL, which serialized in the captured graph):
//   * blocks bid < ZBLKS zero a strided share of out, fence, bump g_done.
//     __launch_bounds__(256,4) guarantees >= 592 resident blocks, so all
//     444 writers are wave-1 resident -> they always make progress -> the
//     join below cannot deadlock.
//   * ALL blocks then stage 4 column-groups of reads into smem (no out
//     access), so x reads stream concurrently with the zero writes and
//     DRAM stays saturated through the zero window.
//   * one spin-join on g_done == ZBLKS, then channel-major commits
//     (R12 sector collapse) for all 4 groups, then the exact fallback
//     (never expected; recomputed from frustum post-join).
__global__ void __launch_bounds__(256, 4)
fused_kernel(const float* __restrict__ x, const float* __restrict__ frustum,
             float* __restrict__ out,
             const float* __restrict__ rots,
             const float* __restrict__ trans,
             const float* __restrict__ intrins) {
    __shared__ float    s_cmb[B_][9];
    __shared__ float    s_tr[B_][3];
    __shared__ float    s_acc[GPB][8][C_];
    __shared__ unsigned s_mask[GPB][8];
    __shared__ unsigned s_q[GPB][8];
    __shared__ unsigned s_b[GPB];
    __shared__ unsigned s_fb[GPB];     // bitmask of warps needing fallback

    unsigned tid  = threadIdx.x;
    unsigned lane = tid & 31u;         // lane == h in phase 1
    unsigned wid  = tid >> 5;
    unsigned bid  = blockIdx.x;

    // --- setup: combine[b] = rots[b] @ inv(intrins[b]) for ALL 4 batches ---
    if (tid < B_) {
        unsigned b = tid;
        const float* K = intrins + b * 9;
        double a00 = K[0], a01 = K[1], a02 = K[2];
        double a10 = K[3], a11 = K[4], a12 = K[5];
        double a20 = K[6], a21 = K[7], a22 = K[8];
        double det = a00 * (a11 * a22 - a12 * a21)
                   - a01 * (a10 * a22 - a12 * a20)
                   + a02 * (a10 * a21 - a11 * a20);
        double id = 1.0 / det;
        float inv[9];
        inv[0] = (float)(( a11 * a22 - a12 * a21) * id);
        inv[1] = (float)((-(a01 * a22 - a02 * a21)) * id);
        inv[2] = (float)(( a01 * a12 - a02 * a11) * id);
        inv[3] = (float)((-(a10 * a22 - a12 * a20)) * id);
        inv[4] = (float)(( a00 * a22 - a02 * a20) * id);
        inv[5] = (float)((-(a00 * a12 - a02 * a10)) * id);
        inv[6] = (float)(( a10 * a21 - a11 * a20) * id);
        inv[7] = (float)((-(a00 * a21 - a01 * a20)) * id);
        inv[8] = (float)(( a00 * a11 - a01 * a10) * id);
        const float* R = rots + b * 9;
        #pragma unroll
        for (int i = 0; i < 3; i++)
            #pragma unroll
            for (int j = 0; j < 3; j++)
                s_cmb[b][i * 3 + j] = R[i * 3 + 0] * inv[0 * 3 + j]
                                    + R[i * 3 + 1] * inv[1 * 3 + j]
                                    + R[i * 3 + 2] * inv[2 * 3 + j];
        s_tr[b][0] = trans[b * 3 + 0];
        s_tr[b][1] = trans[b * 3 + 1];
        s_tr[b][2] = trans[b * 3 + 2];
    }
    if (tid < GPB) s_fb[tid] = 0u;
    __syncthreads();

    // --------------- zero duty (writers are wave-1 resident) ---------------
    if (bid < ZBLKS) {
        const float4 z = make_float4(0.f, 0.f, 0.f, 0.f);
        float4* o4 = reinterpret_cast<float4*>(out);
        for (unsigned i = bid * 256u + tid; i < OUT_N4; i += ZBLKS * 256u)
            o4[i] = z;
        __threadfence();
        __syncthreads();                   // all threads' stores done
        if (tid == 0) atomicAdd(&g_done, 1u);
    }

    // --------------- stage GPB groups: reads only, no out access -----------
    #pragma unroll 1
    for (int s = 0; s < GPB; s++) {
        unsigned grp = bid * GPB + (unsigned)s;
        unsigned col = grp * 8u + wid;     // one column per warp
        unsigned w = col % W_;
        unsigned t = col / W_;
        unsigned d = t % D_;
        unsigned b = t / D_;               // uniform within the group
        if (tid == 0) s_b[s] = b;

        // frustum (D,H,W,3): [..,0]=u (w only), [..,1]=v (h only), [..,2]=depth
        const float* fr = frustum + ((d * H_ + lane) * W_ + w) * 3u;
        float fu = fr[0], fv = fr[1], fd = fr[2];
        float p0 = fu * fd, p1 = fv * fd, p2 = fd;

        const float* cm = s_cmb[b];
        const float* tr = s_tr[b];
        float gx = cm[0] * p0 + cm[1] * p1 + cm[2] * p2 + tr[0];
        float gy = cm[3] * p0 + cm[4] * p1 + cm[5] * p2 + tr[1];
        float gz = cm[6] * p0 + cm[7] * p1 + cm[8] * p2 + tr[2];

        // matches ((geom - BX_LO)/DX).astype(int32): trunc toward zero,
        // incl. the (-1,0)->0 "kept" quirk of the reference
        int cx = (int)((gx + 54.0f) / 0.3f);
        int cy = (int)((gy + 54.0f) / 0.3f);
        int cz = (int)((gz + 10.0f) / 20.0f);

        bool pass = (unsigned)cx < (unsigned)NX_ &&
                    (unsigned)cy < (unsigned)NY_ && cz == 0;
        unsigned mask = __ballot_sync(0xFFFFFFFFu, pass);
        bool live = false;

        if (mask != 0u) {
            int src = __ffs(mask) - 1;
            int cx0 = __shfl_sync(0xFFFFFFFFu, cx, src);
            int cy0 = __shfl_sync(0xFFFFFFFFu, cy, src);
            bool uni = __all_sync(0xFFFFFFFFu,
                                  !pass || (cx == cx0 && cy == cy0));
            if (uni) {
                live = true;
                if (lane == 0) {
                    s_mask[s][wid] = mask;
                    s_q[s][wid]    = (unsigned)cx0 * NY_ + (unsigned)cy0;
                }
            } else {
                if (lane == 0) {
                    s_mask[s][wid] = 0u;
                    atomicOr(&s_fb[s], 1u << wid);   // defer past the join
                }
            }
        } else if (lane == 0) {
            s_mask[s][wid] = 0u;
        }

        unsigned xbase = (((b * D_ + d) * H_) * W_ + w) * (unsigned)C_;
        if (live && lane < C_ / 4) {
            const float* xp = x + xbase + 4u * lane;
            float4 acc = make_float4(0.f, 0.f, 0.f, 0.f);
            #pragma unroll
            for (unsigned h = 0; h < H_; h++) {
                // UNCONDITIONAL load (R14 win): no control dep on the
                // LDG.128 stream; predicated add keeps sums bit-exact.
                float4 v = __ldcs(reinterpret_cast<const float4*>(
                    xp + h * (unsigned)(W_ * C_)));
                if ((mask >> h) & 1u) {
                    acc.x += v.x; acc.y += v.y; acc.z += v.z; acc.w += v.w;
                }
            }
            *reinterpret_cast<float4*>(&s_acc[s][wid][4u * lane]) = acc;
        }
    }
    __syncthreads();                       // masks/q/b/acc visible block-wide

    // --------------- join: all zero writes must be globally visible --------
    if (tid == 0) {
        volatile unsigned* p = &g_done;
        while (*p < ZBLKS) __nanosleep(128);
    }
    __syncthreads();
    __threadfence();                       // acquire side of writers' release

    // --------------- commits: channel-major across 8 adjacent-w columns ----
    // GPB*640 = 2560 tasks = 10 * 256. r&7 = column, r>>3 = channel: 8
    // consecutive lanes share c and hit 8 neighboring q's (R12 collapse).
    #pragma unroll
    for (int k = 0; k < (GPB * 640) / 256; k++) {
        unsigned idx = tid + (unsigned)k * 256u;
        unsigned s   = idx / 640u;
        unsigned r   = idx % 640u;
        unsigned cl  = r & 7u;
        unsigned c   = r >> 3;
        if (s_mask[s][cl] != 0u)
            atomicAdd(out + (s_b[s] * C_ + c) * (unsigned)XY_ + s_q[s][cl],
                      s_acc[s][cl][c]);
    }

    // --------------- exact fallback (never expected), post-join ------------
    #pragma unroll 1
    for (int s = 0; s < GPB; s++) {
        if (s_fb[s] & (1u << wid)) {
            unsigned grp = bid * GPB + (unsigned)s;
            unsigned col = grp * 8u + wid;
            unsigned w = col % W_;
            unsigned t = col / W_;
            unsigned d = t % D_;
            unsigned b = t / D_;
            const float* fr = frustum + ((d * H_ + lane) * W_ + w) * 3u;
            float fu = fr[0], fv = fr[1], fd = fr[2];
            float p0 = fu * fd, p1 = fv * fd, p2 = fd;
            const float* cm = s_cmb[b];
            const float* tr = s_tr[b];
            float gx = cm[0] * p0 + cm[1] * p1 + cm[2] * p2 + tr[0];
            float gy = cm[3] * p0 + cm[4] * p1 + cm[5] * p2 + tr[1];
            float gz = cm[6] * p0 + cm[7] * p1 + cm[8] * p2 + tr[2];
            int cx = (int)((gx + 54.0f) / 0.3f);
            int cy = (int)((gy + 54.0f) / 0.3f);
            int cz = (int)((gz + 10.0f) / 20.0f);
            bool pass = (unsigned)cx < (unsigned)NX_ &&
                        (unsigned)cy < (unsigned)NY_ && cz == 0;
            unsigned mask = __ballot_sync(0xFFFFFFFFu, pass);
            unsigned xbase = (((b * D_ + d) * H_) * W_ + w) * (unsigned)C_;
            for (unsigned h = 0; h < H_; h++) {
                if (!((mask >> h) & 1u)) continue;
                int cxh = __shfl_sync(0xFFFFFFFFu, cx, h);
                int cyh = __shfl_sync(0xFFFFFFFFu, cy, h);
                unsigned q = (unsigned)cxh * NY_ + (unsigned)cyh;
                const float* xr = x + xbase + h * (unsigned)(W_ * C_);
                for (unsigned c = lane; c < C_; c += 32)
                    atomicAdd(out + (b * C_ + c) * (unsigned)XY_ + q, xr[c]);
            }
        }
    }

    // --------------- epilogue: last block resets counters for next replay --
    __syncthreads();
    if (tid == 0) {
        __threadfence();
        if (atomicAdd(&g_exit, 1u) == (unsigned)(GRID_ - 1)) {
            g_done = 0u;
            g_exit = 0u;
            __threadfence();
        }
    }
}

// ---------------- launch ----------------------------------------------------
extern "C" void kernel_launch(void* const* d_in, const int* in_sizes, int n_in,
                              void* d_out, int out_size) {
    const float* x       = (const float*)d_in[0];
    const float* rots    = (const float*)d_in[1];
    const float* trans   = (const float*)d_in[2];
    const float* intrins = (const float*)d_in[3];
    const float* frustum = (const float*)d_in[4];
    float* out = (float*)d_out;

    // single fused launch: zero + scatter with device-side join
    fused_kernel<<<GRID_, 256>>>(x, frustum, out, rots, trans, intrins);
}